// round 5
// baseline (speedup 1.0000x reference)
#include <cuda_runtime.h>
#include <cuda_fp16.h>
#include <cstdint>

// Problem constants
#define Bdim 128
#define Ndim 100000
#define Ddim 128
#define NT   64
#define NBLK ((Ndim + NT - 1) / NT)     // 1563
#define THREADS 256
#define INV_T 14.285714285714285714f

// smem layout (bytes). pitch 272B per row (128 fp16 = 256B + 16B pad)
#define PITCH  272
#define SM_AH  0
#define SM_AL  34816                     // +128*272
#define SM_B   69632                     // +128*272 (B uses 64 rows = 17408)
#define SM_RACC 87040                    // 2*128 floats
#define SM_TOTAL 88064

// Scratch
__device__ float g_partial[Bdim * NBLK];
__device__ float g_invsum[Bdim];

// ---------------- helpers ----------------
__device__ __forceinline__ float f16_rn_f(float v) {
    return __half2float(__float2half_rn(v));
}
// pack two f32 into f16x2: first arg -> low 16 bits
__device__ __forceinline__ uint32_t pack2(float lo, float hi) {
    uint32_t r;
    asm("cvt.rn.f16x2.f32 %0, %1, %2;" : "=r"(r) : "f"(hi), "f"(lo));
    return r;
}
__device__ __forceinline__ void mma_f16(float* d, const uint32_t* a, const uint32_t* b) {
    asm volatile(
        "mma.sync.aligned.m16n8k16.row.col.f32.f16.f16.f32 "
        "{%0,%1,%2,%3}, {%4,%5,%6,%7}, {%8,%9}, {%0,%1,%2,%3};"
        : "+f"(d[0]), "+f"(d[1]), "+f"(d[2]), "+f"(d[3])
        : "r"(a[0]), "r"(a[1]), "r"(a[2]), "r"(a[3]), "r"(b[0]), "r"(b[1]));
}

// ---------------------------------------------------------------------------
// Pass 1: fp16-split tensor GEMM (mma.sync, 2 passes) + exp + row sums + mask
// Block: 256 thr, tile 128(M) x 64(N). Warp grid 4(M) x 2(N), warp tile 32x32.
// ---------------------------------------------------------------------------
__global__ void __launch_bounds__(THREADS, 2)
k_gemm(const float* __restrict__ x, const float* __restrict__ mda,
       const int* __restrict__ labels, float* __restrict__ out) {
    extern __shared__ char smem[];
    const int tid  = threadIdx.x;
    const int wid  = tid >> 5;
    const int lane = tid & 31;
    const int n0   = blockIdx.x * NT;

    // ---- stage A = x (hi/lo fp16 split), float4 loads ----
    {
        const float4* xv = reinterpret_cast<const float4*>(x);
        for (int i = tid; i < (Bdim * Ddim) / 4; i += THREADS) {
            float4 v = xv[i];
            int b = i >> 5, k = (i & 31) * 4;
            float hx = f16_rn_f(v.x), hy = f16_rn_f(v.y);
            float hz = f16_rn_f(v.z), hw = f16_rn_f(v.w);
            char* pa = smem + (size_t)b * PITCH + k * 2;
            *(uint32_t*)(pa + SM_AH)     = pack2(hx, hy);
            *(uint32_t*)(pa + SM_AH + 4) = pack2(hz, hw);
            *(uint32_t*)(pa + SM_AL)     = pack2(v.x - hx, v.y - hy);
            *(uint32_t*)(pa + SM_AL + 4) = pack2(v.z - hz, v.w - hw);
        }
    }

    // ---- stage B = feats tile (single fp16), streaming loads ----
    {
#pragma unroll
        for (int j = 0; j < (NT * Ddim) / THREADS; ++j) {
            int e = tid + THREADS * j;
            int nl = e >> 7, k = e & 127;
            int n = n0 + nl;
            float v = (n < Ndim) ? __ldcs(mda + (size_t)n * 129 + 1 + k) : 0.0f;
            *(__half*)(smem + SM_B + (size_t)nl * PITCH + k * 2) = __float2half_rn(v);
        }
    }
    __syncthreads();

    // ---- warp tiling ----
    const int wm = wid >> 1, wn = wid & 1;
    const int gid = lane >> 2, tg = lane & 3;

    const char* aB = smem + (size_t)(wm * 32 + gid) * PITCH + tg * 4;
    const char* bB = smem + (size_t)(wn * 32 + gid) * PITCH + tg * 4;

    float acc[2][4][4];
#pragma unroll
    for (int mi = 0; mi < 2; ++mi)
#pragma unroll
        for (int ni = 0; ni < 4; ++ni)
#pragma unroll
            for (int r = 0; r < 4; ++r) acc[mi][ni][r] = 0.0f;

#pragma unroll
    for (int ks = 0; ks < 8; ++ks) {
        const int ko = ks * 32;     // 16 k * 2 bytes
        uint32_t ah[2][4], al[2][4], bh[4][2];
#pragma unroll
        for (int mi = 0; mi < 2; ++mi) {
            const char* p = aB + mi * (16 * PITCH) + ko;
            ah[mi][0] = *(const uint32_t*)(p + SM_AH);
            ah[mi][1] = *(const uint32_t*)(p + SM_AH + 8 * PITCH);
            ah[mi][2] = *(const uint32_t*)(p + SM_AH + 16);
            ah[mi][3] = *(const uint32_t*)(p + SM_AH + 8 * PITCH + 16);
            al[mi][0] = *(const uint32_t*)(p + SM_AL);
            al[mi][1] = *(const uint32_t*)(p + SM_AL + 8 * PITCH);
            al[mi][2] = *(const uint32_t*)(p + SM_AL + 16);
            al[mi][3] = *(const uint32_t*)(p + SM_AL + 8 * PITCH + 16);
        }
#pragma unroll
        for (int ni = 0; ni < 4; ++ni) {
            const char* p = bB + ni * (8 * PITCH) + ko;
            bh[ni][0] = *(const uint32_t*)(p + SM_B);
            bh[ni][1] = *(const uint32_t*)(p + SM_B + 16);
        }
#pragma unroll
        for (int mi = 0; mi < 2; ++mi)
#pragma unroll
            for (int ni = 0; ni < 4; ++ni) {
                mma_f16(acc[mi][ni], ah[mi], bh[ni]);
                mma_f16(acc[mi][ni], al[mi], bh[ni]);
            }
    }

    // ---- epilogue: exp, store, row partial sums ----
    float* racc = (float*)(smem + SM_RACC);
    float rs[2][2] = {{0.0f, 0.0f}, {0.0f, 0.0f}};
#pragma unroll
    for (int mi = 0; mi < 2; ++mi) {
        const int m_lo = wm * 32 + mi * 16 + gid;
#pragma unroll
        for (int ni = 0; ni < 4; ++ni) {
            const int ng = n0 + wn * 32 + ni * 8 + tg * 2;
            const bool ok = ng < Ndim;              // Ndim even -> pair guard
            float e0 = ok ? __expf(acc[mi][ni][0] * INV_T) : 0.0f;
            float e1 = ok ? __expf(acc[mi][ni][1] * INV_T) : 0.0f;
            float e2 = ok ? __expf(acc[mi][ni][2] * INV_T) : 0.0f;
            float e3 = ok ? __expf(acc[mi][ni][3] * INV_T) : 0.0f;
            if (ok) {
                *(float2*)(out + (size_t)m_lo * Ndim + ng)       = make_float2(e0, e1);
                *(float2*)(out + (size_t)(m_lo + 8) * Ndim + ng) = make_float2(e2, e3);
            }
            rs[mi][0] += e0 + e1;
            rs[mi][1] += e2 + e3;
        }
    }

    // ---- mask write (independent of Z): m[b][n] = (mda[n*129] == label[b]) ----
    {
        const int n = n0 + lane * 2;
        if (n + 1 < Ndim) {
            float c0 = __ldg(mda + (size_t)n * 129);
            float c1 = __ldg(mda + (size_t)(n + 1) * 129);
            float* mbase = out + (size_t)Bdim * Ndim;
#pragma unroll
            for (int r = 0; r < 16; ++r) {
                const int b = wid + r * 8;
                const float lb = (float)__ldg(labels + b);
                float2 m = make_float2(c0 == lb ? 1.0f : 0.0f,
                                       c1 == lb ? 1.0f : 0.0f);
                __stcs((float2*)(mbase + (size_t)b * Ndim + n), m);
            }
        }
    }

#pragma unroll
    for (int mi = 0; mi < 2; ++mi) {
#pragma unroll
        for (int o = 1; o <= 2; o <<= 1) {
            rs[mi][0] += __shfl_xor_sync(0xffffffffu, rs[mi][0], o);
            rs[mi][1] += __shfl_xor_sync(0xffffffffu, rs[mi][1], o);
        }
        if (tg == 0) {
            const int m_lo = wm * 32 + mi * 16 + gid;
            racc[wn * 128 + m_lo]     = rs[mi][0];
            racc[wn * 128 + m_lo + 8] = rs[mi][1];
        }
    }
    __syncthreads();
    if (tid < 128)
        g_partial[(size_t)tid * NBLK + blockIdx.x] = racc[tid] + racc[128 + tid];
}

// ---------------------------------------------------------------------------
// Pass 2: deterministic reduction of per-block partials
// ---------------------------------------------------------------------------
__global__ void k_reduce() {
    __shared__ float sh[256];
    const int b = blockIdx.x, t = threadIdx.x;
    float s = 0.0f;
    for (int i = t; i < NBLK; i += 256) s += g_partial[(size_t)b * NBLK + i];
    sh[t] = s;
    __syncthreads();
    for (int o = 128; o > 0; o >>= 1) {
        if (t < o) sh[t] += sh[t + o];
        __syncthreads();
    }
    if (t == 0) g_invsum[b] = 1.0f / sh[0];
}

// ---------------------------------------------------------------------------
// Pass 3: in-place normalize only (mask already written by k_gemm)
// ---------------------------------------------------------------------------
__global__ void __launch_bounds__(256)
k_norm(float* __restrict__ out) {
    const int b = blockIdx.y;
    const float inv = g_invsum[b];
    const int f0 = blockIdx.x * 1024 + threadIdx.x;
    const int NF4 = Ndim / 4;

    float4* orow = reinterpret_cast<float4*>(out + (size_t)b * Ndim);

    float4 v[4];
    bool ok[4];
#pragma unroll
    for (int j = 0; j < 4; ++j) {
        int f = f0 + 256 * j;
        ok[j] = f < NF4;
        if (ok[j]) v[j] = orow[f];
    }
#pragma unroll
    for (int j = 0; j < 4; ++j) {
        if (!ok[j]) continue;
        int f = f0 + 256 * j;
        float4 t = v[j];
        t.x *= inv; t.y *= inv; t.z *= inv; t.w *= inv;
        orow[f] = t;
    }
}

// ---------------------------------------------------------------------------
extern "C" void kernel_launch(void* const* d_in, const int* in_sizes, int n_in,
                              void* d_out, int out_size) {
    const float* x      = (const float*)d_in[0];   // [128,128]
    const int*   labels = (const int*)  d_in[2];   // [128]
    const float* mda    = (const float*)d_in[3];   // [100000,129]
    float*       out    = (float*)d_out;

    cudaFuncSetAttribute(k_gemm, cudaFuncAttributeMaxDynamicSharedMemorySize, SM_TOTAL);

    k_gemm<<<NBLK, THREADS, SM_TOTAL>>>(x, mda, labels, out);
    k_reduce<<<Bdim, 256>>>();
    dim3 ngrid((Ndim / 4 + 1023) / 1024, Bdim);
    k_norm<<<ngrid, 256>>>(out);
}

// round 6
// speedup vs baseline: 1.0487x; 1.0487x over previous
#include <cuda_runtime.h>
#include <cuda_fp16.h>
#include <cstdint>

// Problem constants
#define Bdim 128
#define Ndim 100000
#define Ddim 128
#define NT   64
#define NBLK ((Ndim + NT - 1) / NT)     // 1563
#define THREADS 256
#define INV_T 14.285714285714285714f

// smem layout (bytes). pitch 272B per row (128 fp16 = 256B + 16B pad)
#define PITCH  272
#define SM_AH  0
#define SM_AL  34816                     // +128*272
#define SM_B   69632                     // +128*272 (B uses 64 rows = 17408)
#define SM_RACC 87040                    // 2*128 floats
#define SM_TOTAL 88064

// Scratch
__device__ float g_partial[Bdim * NBLK];
__device__ float g_invsum[Bdim];

// ---------------- helpers ----------------
__device__ __forceinline__ float f16_rn_f(float v) {
    return __half2float(__float2half_rn(v));
}
// pack two f32 into f16x2: first arg -> low 16 bits
__device__ __forceinline__ uint32_t pack2(float lo, float hi) {
    uint32_t r;
    asm("cvt.rn.f16x2.f32 %0, %1, %2;" : "=r"(r) : "f"(hi), "f"(lo));
    return r;
}
__device__ __forceinline__ void mma_f16(float* d, const uint32_t* a, const uint32_t* b) {
    asm volatile(
        "mma.sync.aligned.m16n8k16.row.col.f32.f16.f16.f32 "
        "{%0,%1,%2,%3}, {%4,%5,%6,%7}, {%8,%9}, {%0,%1,%2,%3};"
        : "+f"(d[0]), "+f"(d[1]), "+f"(d[2]), "+f"(d[3])
        : "r"(a[0]), "r"(a[1]), "r"(a[2]), "r"(a[3]), "r"(b[0]), "r"(b[1]));
}

// ---------------------------------------------------------------------------
// Pass 1: fp16-split tensor GEMM (mma.sync, 2 passes) + exp + row sums + mask
// Block: 256 thr, tile 128(M) x 64(N). Warp grid 4(M) x 2(N), warp tile 32x32.
// ---------------------------------------------------------------------------
__global__ void __launch_bounds__(THREADS, 2)
k_gemm(const float* __restrict__ x, const float* __restrict__ mda,
       const int* __restrict__ labels, float* __restrict__ out) {
    extern __shared__ char smem[];
    const int tid  = threadIdx.x;
    const int wid  = tid >> 5;
    const int lane = tid & 31;
    const int n0   = blockIdx.x * NT;

    // ---- stage A = x (hi/lo fp16 split), float4 loads ----
    {
        const float4* xv = reinterpret_cast<const float4*>(x);
        for (int i = tid; i < (Bdim * Ddim) / 4; i += THREADS) {
            float4 v = xv[i];
            int b = i >> 5, k = (i & 31) * 4;
            float hx = f16_rn_f(v.x), hy = f16_rn_f(v.y);
            float hz = f16_rn_f(v.z), hw = f16_rn_f(v.w);
            char* pa = smem + (size_t)b * PITCH + k * 2;
            *(uint32_t*)(pa + SM_AH)     = pack2(hx, hy);
            *(uint32_t*)(pa + SM_AH + 4) = pack2(hz, hw);
            *(uint32_t*)(pa + SM_AL)     = pack2(v.x - hx, v.y - hy);
            *(uint32_t*)(pa + SM_AL + 4) = pack2(v.z - hz, v.w - hw);
        }
    }

    // ---- stage B = feats tile (single fp16), streaming loads ----
    {
#pragma unroll
        for (int j = 0; j < (NT * Ddim) / THREADS; ++j) {
            int e = tid + THREADS * j;
            int nl = e >> 7, k = e & 127;
            int n = n0 + nl;
            float v = (n < Ndim) ? __ldcs(mda + (size_t)n * 129 + 1 + k) : 0.0f;
            *(__half*)(smem + SM_B + (size_t)nl * PITCH + k * 2) = __float2half_rn(v);
        }
    }
    __syncthreads();

    // ---- warp tiling ----
    const int wm = wid >> 1, wn = wid & 1;
    const int gid = lane >> 2, tg = lane & 3;

    const char* aB = smem + (size_t)(wm * 32 + gid) * PITCH + tg * 4;
    const char* bB = smem + (size_t)(wn * 32 + gid) * PITCH + tg * 4;

    float acc[2][4][4];
#pragma unroll
    for (int mi = 0; mi < 2; ++mi)
#pragma unroll
        for (int ni = 0; ni < 4; ++ni)
#pragma unroll
            for (int r = 0; r < 4; ++r) acc[mi][ni][r] = 0.0f;

#pragma unroll
    for (int ks = 0; ks < 8; ++ks) {
        const int ko = ks * 32;     // 16 k * 2 bytes
        uint32_t ah[2][4], al[2][4], bh[4][2];
#pragma unroll
        for (int mi = 0; mi < 2; ++mi) {
            const char* p = aB + mi * (16 * PITCH) + ko;
            ah[mi][0] = *(const uint32_t*)(p + SM_AH);
            ah[mi][1] = *(const uint32_t*)(p + SM_AH + 8 * PITCH);
            ah[mi][2] = *(const uint32_t*)(p + SM_AH + 16);
            ah[mi][3] = *(const uint32_t*)(p + SM_AH + 8 * PITCH + 16);
            al[mi][0] = *(const uint32_t*)(p + SM_AL);
            al[mi][1] = *(const uint32_t*)(p + SM_AL + 8 * PITCH);
            al[mi][2] = *(const uint32_t*)(p + SM_AL + 16);
            al[mi][3] = *(const uint32_t*)(p + SM_AL + 8 * PITCH + 16);
        }
#pragma unroll
        for (int ni = 0; ni < 4; ++ni) {
            const char* p = bB + ni * (8 * PITCH) + ko;
            bh[ni][0] = *(const uint32_t*)(p + SM_B);
            bh[ni][1] = *(const uint32_t*)(p + SM_B + 16);
        }
#pragma unroll
        for (int mi = 0; mi < 2; ++mi)
#pragma unroll
            for (int ni = 0; ni < 4; ++ni) {
                mma_f16(acc[mi][ni], ah[mi], bh[ni]);
                mma_f16(acc[mi][ni], al[mi], bh[ni]);
            }
    }

    // ---- epilogue: exp, store, row partial sums ----
    float* racc = (float*)(smem + SM_RACC);
    float rs[2][2] = {{0.0f, 0.0f}, {0.0f, 0.0f}};
#pragma unroll
    for (int mi = 0; mi < 2; ++mi) {
        const int m_lo = wm * 32 + mi * 16 + gid;
#pragma unroll
        for (int ni = 0; ni < 4; ++ni) {
            const int ng = n0 + wn * 32 + ni * 8 + tg * 2;
            const bool ok = ng < Ndim;              // Ndim even -> pair guard
            float e0 = ok ? __expf(acc[mi][ni][0] * INV_T) : 0.0f;
            float e1 = ok ? __expf(acc[mi][ni][1] * INV_T) : 0.0f;
            float e2 = ok ? __expf(acc[mi][ni][2] * INV_T) : 0.0f;
            float e3 = ok ? __expf(acc[mi][ni][3] * INV_T) : 0.0f;
            if (ok) {
                *(float2*)(out + (size_t)m_lo * Ndim + ng)       = make_float2(e0, e1);
                *(float2*)(out + (size_t)(m_lo + 8) * Ndim + ng) = make_float2(e2, e3);
            }
            rs[mi][0] += e0 + e1;
            rs[mi][1] += e2 + e3;
        }
    }

    // ---- mask write (independent of Z): m[b][n] = (mda[n*129] == label[b]) ----
    {
        const int n = n0 + lane * 2;
        if (n + 1 < Ndim) {
            float c0 = __ldg(mda + (size_t)n * 129);
            float c1 = __ldg(mda + (size_t)(n + 1) * 129);
            float* mbase = out + (size_t)Bdim * Ndim;
#pragma unroll
            for (int r = 0; r < 16; ++r) {
                const int b = wid + r * 8;
                const float lb = (float)__ldg(labels + b);
                float2 m = make_float2(c0 == lb ? 1.0f : 0.0f,
                                       c1 == lb ? 1.0f : 0.0f);
                __stcs((float2*)(mbase + (size_t)b * Ndim + n), m);
            }
        }
    }

#pragma unroll
    for (int mi = 0; mi < 2; ++mi) {
#pragma unroll
        for (int o = 1; o <= 2; o <<= 1) {
            rs[mi][0] += __shfl_xor_sync(0xffffffffu, rs[mi][0], o);
            rs[mi][1] += __shfl_xor_sync(0xffffffffu, rs[mi][1], o);
        }
        if (tg == 0) {
            const int m_lo = wm * 32 + mi * 16 + gid;
            racc[wn * 128 + m_lo]     = rs[mi][0];
            racc[wn * 128 + m_lo + 8] = rs[mi][1];
        }
    }
    __syncthreads();
    if (tid < 128)
        g_partial[(size_t)tid * NBLK + blockIdx.x] = racc[tid] + racc[128 + tid];
}

// ---------------------------------------------------------------------------
// Pass 2: deterministic reduction of per-block partials
// ---------------------------------------------------------------------------
__global__ void k_reduce() {
    __shared__ float sh[256];
    const int b = blockIdx.x, t = threadIdx.x;
    float s = 0.0f;
    for (int i = t; i < NBLK; i += 256) s += g_partial[(size_t)b * NBLK + i];
    sh[t] = s;
    __syncthreads();
    for (int o = 128; o > 0; o >>= 1) {
        if (t < o) sh[t] += sh[t + o];
        __syncthreads();
    }
    if (t == 0) g_invsum[b] = 1.0f / sh[0];
}

// ---------------------------------------------------------------------------
// Pass 3: in-place normalize only (mask already written by k_gemm)
// ---------------------------------------------------------------------------
__global__ void __launch_bounds__(256)
k_norm(float* __restrict__ out) {
    const int b = blockIdx.y;
    const float inv = g_invsum[b];
    const int f0 = blockIdx.x * 1024 + threadIdx.x;
    const int NF4 = Ndim / 4;

    float4* orow = reinterpret_cast<float4*>(out + (size_t)b * Ndim);

    float4 v[4];
    bool ok[4];
#pragma unroll
    for (int j = 0; j < 4; ++j) {
        int f = f0 + 256 * j;
        ok[j] = f < NF4;
        if (ok[j]) v[j] = orow[f];
    }
#pragma unroll
    for (int j = 0; j < 4; ++j) {
        if (!ok[j]) continue;
        int f = f0 + 256 * j;
        float4 t = v[j];
        t.x *= inv; t.y *= inv; t.z *= inv; t.w *= inv;
        orow[f] = t;
    }
}

// ---------------------------------------------------------------------------
extern "C" void kernel_launch(void* const* d_in, const int* in_sizes, int n_in,
                              void* d_out, int out_size) {
    const float* x      = (const float*)d_in[0];   // [128,128]
    const int*   labels = (const int*)  d_in[2];   // [128]
    const float* mda    = (const float*)d_in[3];   // [100000,129]
    float*       out    = (float*)d_out;

    cudaFuncSetAttribute(k_gemm, cudaFuncAttributeMaxDynamicSharedMemorySize, SM_TOTAL);

    k_gemm<<<NBLK, THREADS, SM_TOTAL>>>(x, mda, labels, out);
    k_reduce<<<Bdim, 256>>>();
    dim3 ngrid((Ndim / 4 + 1023) / 1024, Bdim);
    k_norm<<<ngrid, 256>>>(out);
}

// round 7
// speedup vs baseline: 1.2991x; 1.2388x over previous
#include <cuda_runtime.h>
#include <cuda_fp16.h>
#include <cstdint>

// Problem constants
#define Bdim 128
#define Ndim 100000
#define Ddim 128
#define NT   64
#define NTILES ((Ndim + NT - 1) / NT)   // 1563
#define GRID 304                        // persistent: 2 CTAs/SM x 152 SMs
#define THREADS 256
#define INV_T 14.285714285714285714f

// smem layout (bytes). pitch 272B per row (128 fp16 = 256B + 16B pad)
#define PITCH  272
#define SM_AH  0
#define SM_AL  34816                    // +128*272
#define SM_B   69632                    // 2 buffers x 64*272 = 17408 each
#define SM_RACC 104448                  // 256 floats
#define SM_TOTAL 105472

// Scratch
__device__ float g_partial[Bdim * GRID];
__device__ float g_invsum[Bdim];

// ---------------- helpers ----------------
__device__ __forceinline__ float f16_rn_f(float v) {
    return __half2float(__float2half_rn(v));
}
__device__ __forceinline__ uint32_t pack2(float lo, float hi) {
    uint32_t r;
    asm("cvt.rn.f16x2.f32 %0, %1, %2;" : "=r"(r) : "f"(hi), "f"(lo));
    return r;
}
__device__ __forceinline__ void mma_f16(float* d, const uint32_t* a, const uint32_t* b) {
    asm volatile(
        "mma.sync.aligned.m16n8k16.row.col.f32.f16.f16.f32 "
        "{%0,%1,%2,%3}, {%4,%5,%6,%7}, {%8,%9}, {%0,%1,%2,%3};"
        : "+f"(d[0]), "+f"(d[1]), "+f"(d[2]), "+f"(d[3])
        : "r"(a[0]), "r"(a[1]), "r"(a[2]), "r"(a[3]), "r"(b[0]), "r"(b[1]));
}

// ---------------------------------------------------------------------------
// Pass 1: persistent fp16-split tensor GEMM + exp + row sums + mask
// 304 CTAs, each loops over tiles t = cta, cta+GRID, ... (NT=64 cols each).
// Block tile 128(M) x 64(N); warp grid 4(M) x 2(N); warp tile 32x32.
// B double-buffered in smem; next tile prefetched into registers during MMA.
// ---------------------------------------------------------------------------
__global__ void __launch_bounds__(THREADS, 2)
k_gemm(const float* __restrict__ x, const float* __restrict__ mda,
       const int* __restrict__ labels, float* __restrict__ out) {
    extern __shared__ char smem[];
    const int tid  = threadIdx.x;
    const int wid  = tid >> 5;
    const int lane = tid & 31;
    const int cta  = blockIdx.x;
    const int cnt  = (NTILES - cta + GRID - 1) / GRID;

    // ---- prefetch tile 0 into registers (overlaps A staging) ----
    float pf[32];
    {
        const int t0 = cta;
        const float* src = mda + (size_t)t0 * NT * 129 + 1;
        const bool tail = (t0 == NTILES - 1);
#pragma unroll
        for (int j = 0; j < 32; ++j) {
            int e = tid + THREADS * j;
            int nl = e >> 7, k = e & 127;
            pf[j] = (!tail || (t0 * NT + nl) < Ndim)
                        ? __ldcs(src + (size_t)nl * 129 + k) : 0.0f;
        }
    }

    // ---- stage A = x (hi/lo fp16 split) once ----
    {
        const float4* xv = reinterpret_cast<const float4*>(x);
        for (int i = tid; i < (Bdim * Ddim) / 4; i += THREADS) {
            float4 v = xv[i];
            int b = i >> 5, k = (i & 31) * 4;
            float hx = f16_rn_f(v.x), hy = f16_rn_f(v.y);
            float hz = f16_rn_f(v.z), hw = f16_rn_f(v.w);
            char* pa = smem + (size_t)b * PITCH + k * 2;
            *(uint32_t*)(pa + SM_AH)     = pack2(hx, hy);
            *(uint32_t*)(pa + SM_AH + 4) = pack2(hz, hw);
            *(uint32_t*)(pa + SM_AL)     = pack2(v.x - hx, v.y - hy);
            *(uint32_t*)(pa + SM_AL + 4) = pack2(v.z - hz, v.w - hw);
        }
    }

    // ---- warp tiling constants ----
    const int wm = wid >> 1, wn = wid & 1;
    const int gid = lane >> 2, tg = lane & 3;
    const char* aB = smem + (size_t)(wm * 32 + gid) * PITCH + tg * 4;

    float rs[2][2] = {{0.0f, 0.0f}, {0.0f, 0.0f}};   // running row sums

    for (int i = 0; i < cnt; ++i) {
        const int t  = cta + i * GRID;
        const int bi = i & 1;
        const int n0 = t * NT;
        char* bbuf = smem + SM_B + bi * 17408;

        // ---- store prefetched tile into B[bi] as fp16 ----
        // (safe: any warp here has passed the previous iteration's barrier,
        //  so no warp is still reading B[bi] from iteration i-2)
        __syncthreads();
#pragma unroll
        for (int j = 0; j < 32; ++j) {
            int e = tid + THREADS * j;
            int nl = e >> 7, k = e & 127;
            *(__half*)(bbuf + (size_t)nl * PITCH + k * 2) = __float2half_rn(pf[j]);
        }

        // ---- prefetch next tile (hides DRAM latency under MMA) ----
        if (i + 1 < cnt) {
            const int tn = t + GRID;
            const float* src = mda + (size_t)tn * NT * 129 + 1;
            if (tn == NTILES - 1) {
#pragma unroll
                for (int j = 0; j < 32; ++j) {
                    int e = tid + THREADS * j;
                    int nl = e >> 7, k = e & 127;
                    pf[j] = ((tn * NT + nl) < Ndim)
                                ? __ldcs(src + (size_t)nl * 129 + k) : 0.0f;
                }
            } else {
#pragma unroll
                for (int j = 0; j < 32; ++j) {
                    int e = tid + THREADS * j;
                    int nl = e >> 7, k = e & 127;
                    pf[j] = __ldcs(src + (size_t)nl * 129 + k);
                }
            }
        }
        __syncthreads();   // B[bi] ready

        // ---- MMA over B[bi] ----
        const char* bB = bbuf + (size_t)(wn * 32 + gid) * PITCH + tg * 4;
        float acc[2][4][4];
#pragma unroll
        for (int mi = 0; mi < 2; ++mi)
#pragma unroll
            for (int ni = 0; ni < 4; ++ni)
#pragma unroll
                for (int r = 0; r < 4; ++r) acc[mi][ni][r] = 0.0f;

#pragma unroll
        for (int ks = 0; ks < 8; ++ks) {
            const int ko = ks * 32;
            uint32_t ah[2][4], al[2][4], bh[4][2];
#pragma unroll
            for (int mi = 0; mi < 2; ++mi) {
                const char* p = aB + mi * (16 * PITCH) + ko;
                ah[mi][0] = *(const uint32_t*)(p + SM_AH);
                ah[mi][1] = *(const uint32_t*)(p + SM_AH + 8 * PITCH);
                ah[mi][2] = *(const uint32_t*)(p + SM_AH + 16);
                ah[mi][3] = *(const uint32_t*)(p + SM_AH + 8 * PITCH + 16);
                al[mi][0] = *(const uint32_t*)(p + SM_AL);
                al[mi][1] = *(const uint32_t*)(p + SM_AL + 8 * PITCH);
                al[mi][2] = *(const uint32_t*)(p + SM_AL + 16);
                al[mi][3] = *(const uint32_t*)(p + SM_AL + 8 * PITCH + 16);
            }
#pragma unroll
            for (int ni = 0; ni < 4; ++ni) {
                const char* p = bB + ni * (8 * PITCH) + ko;
                bh[ni][0] = *(const uint32_t*)p;
                bh[ni][1] = *(const uint32_t*)(p + 16);
            }
#pragma unroll
            for (int mi = 0; mi < 2; ++mi)
#pragma unroll
                for (int ni = 0; ni < 4; ++ni) {
                    mma_f16(acc[mi][ni], ah[mi], bh[ni]);
                    mma_f16(acc[mi][ni], al[mi], bh[ni]);
                }
        }

        // ---- epilogue: exp, store out, accumulate running row sums ----
#pragma unroll
        for (int mi = 0; mi < 2; ++mi) {
            const int m_lo = wm * 32 + mi * 16 + gid;
#pragma unroll
            for (int ni = 0; ni < 4; ++ni) {
                const int ng = n0 + wn * 32 + ni * 8 + tg * 2;
                const bool ok = ng < Ndim;
                float e0 = ok ? __expf(acc[mi][ni][0] * INV_T) : 0.0f;
                float e1 = ok ? __expf(acc[mi][ni][1] * INV_T) : 0.0f;
                float e2 = ok ? __expf(acc[mi][ni][2] * INV_T) : 0.0f;
                float e3 = ok ? __expf(acc[mi][ni][3] * INV_T) : 0.0f;
                if (ok) {
                    *(float2*)(out + (size_t)m_lo * Ndim + ng)       = make_float2(e0, e1);
                    *(float2*)(out + (size_t)(m_lo + 8) * Ndim + ng) = make_float2(e2, e3);
                }
                rs[mi][0] += e0 + e1;
                rs[mi][1] += e2 + e3;
            }
        }

        // ---- mask write for this tile (independent of Z) ----
        {
            const int n = n0 + lane * 2;
            if (n + 1 < Ndim) {
                float c0 = __ldg(mda + (size_t)n * 129);
                float c1 = __ldg(mda + (size_t)(n + 1) * 129);
                float* mbase = out + (size_t)Bdim * Ndim;
#pragma unroll
                for (int r = 0; r < 16; ++r) {
                    const int b = wid + r * 8;
                    const float lb = (float)__ldg(labels + b);
                    float2 m = make_float2(c0 == lb ? 1.0f : 0.0f,
                                           c1 == lb ? 1.0f : 0.0f);
                    __stcs((float2*)(mbase + (size_t)b * Ndim + n), m);
                }
            }
        }
    }

    // ---- fold running sums: shfl across tg, stash, combine wn halves ----
    float* racc = (float*)(smem + SM_RACC);
    __syncthreads();   // B buffers dead; reuse barrier before racc writes
#pragma unroll
    for (int mi = 0; mi < 2; ++mi) {
#pragma unroll
        for (int o = 1; o <= 2; o <<= 1) {
            rs[mi][0] += __shfl_xor_sync(0xffffffffu, rs[mi][0], o);
            rs[mi][1] += __shfl_xor_sync(0xffffffffu, rs[mi][1], o);
        }
        if (tg == 0) {
            const int m_lo = wm * 32 + mi * 16 + gid;
            racc[wn * 128 + m_lo]     = rs[mi][0];
            racc[wn * 128 + m_lo + 8] = rs[mi][1];
        }
    }
    __syncthreads();
    if (tid < 128)
        g_partial[(size_t)tid * GRID + cta] = racc[tid] + racc[128 + tid];
}

// ---------------------------------------------------------------------------
// Pass 2: deterministic reduction of per-CTA partials
// ---------------------------------------------------------------------------
__global__ void k_reduce() {
    __shared__ float sh[256];
    const int b = blockIdx.x, t = threadIdx.x;
    float s = 0.0f;
    for (int i = t; i < GRID; i += 256) s += g_partial[(size_t)b * GRID + i];
    sh[t] = s;
    __syncthreads();
    for (int o = 128; o > 0; o >>= 1) {
        if (t < o) sh[t] += sh[t + o];
        __syncthreads();
    }
    if (t == 0) g_invsum[b] = 1.0f / sh[0];
}

// ---------------------------------------------------------------------------
// Pass 3: in-place normalize (mask already written by k_gemm)
// ---------------------------------------------------------------------------
__global__ void __launch_bounds__(256)
k_norm(float* __restrict__ out) {
    const int b = blockIdx.y;
    const float inv = g_invsum[b];
    const int f0 = blockIdx.x * 1024 + threadIdx.x;
    const int NF4 = Ndim / 4;

    float4* orow = reinterpret_cast<float4*>(out + (size_t)b * Ndim);

    float4 v[4];
    bool ok[4];
#pragma unroll
    for (int j = 0; j < 4; ++j) {
        int f = f0 + 256 * j;
        ok[j] = f < NF4;
        if (ok[j]) v[j] = orow[f];
    }
#pragma unroll
    for (int j = 0; j < 4; ++j) {
        if (!ok[j]) continue;
        int f = f0 + 256 * j;
        float4 t = v[j];
        t.x *= inv; t.y *= inv; t.z *= inv; t.w *= inv;
        orow[f] = t;
    }
}

// ---------------------------------------------------------------------------
extern "C" void kernel_launch(void* const* d_in, const int* in_sizes, int n_in,
                              void* d_out, int out_size) {
    const float* x      = (const float*)d_in[0];   // [128,128]
    const int*   labels = (const int*)  d_in[2];   // [128]
    const float* mda    = (const float*)d_in[3];   // [100000,129]
    float*       out    = (float*)d_out;

    cudaFuncSetAttribute(k_gemm, cudaFuncAttributeMaxDynamicSharedMemorySize, SM_TOTAL);

    k_gemm<<<GRID, THREADS, SM_TOTAL>>>(x, mda, labels, out);
    k_reduce<<<Bdim, 256>>>();
    dim3 ngrid((Ndim / 4 + 1023) / 1024, Bdim);
    k_norm<<<ngrid, 256>>>(out);
}

// round 12
// speedup vs baseline: 1.6344x; 1.2581x over previous
#include <cuda_runtime.h>
#include <cuda_fp16.h>
#include <cstdint>

// Problem constants
#define Bdim 128
#define Ndim 100000
#define Ddim 128
#define NT   64
#define NTILES ((Ndim + NT - 1) / NT)   // 1563
#define GRID 304                        // persistent: 2 CTAs/SM x 152 SMs
#define THREADS 256
#define INV_T 14.285714285714285714f

// smem layout (bytes). pitch 272B per row (128 fp16 = 256B + 16B pad)
#define PITCH  272
#define SM_A   0                        // A hi only: 128*272 = 34816
#define SM_B   34816                    // 2 buffers x 64*272 = 17408 each
#define SM_RACC 69632                   // 256 floats
#define SM_TOTAL 70656

// Scratch
__device__ float g_partial[Bdim * GRID];
__device__ float g_invsum[Bdim];

// ---------------- helpers ----------------
__device__ __forceinline__ uint32_t pack2(float lo, float hi) {
    uint32_t r;
    asm("cvt.rn.f16x2.f32 %0, %1, %2;" : "=r"(r) : "f"(hi), "f"(lo));
    return r;
}
__device__ __forceinline__ void ldsm4(uint32_t* r, uint32_t addr) {
    asm volatile("ldmatrix.sync.aligned.m8n8.x4.shared.b16 {%0,%1,%2,%3}, [%4];"
        : "=r"(r[0]), "=r"(r[1]), "=r"(r[2]), "=r"(r[3]) : "r"(addr));
}
__device__ __forceinline__ void mma_f16(float* d, const uint32_t* a, const uint32_t* b) {
    asm volatile(
        "mma.sync.aligned.m16n8k16.row.col.f32.f16.f16.f32 "
        "{%0,%1,%2,%3}, {%4,%5,%6,%7}, {%8,%9}, {%0,%1,%2,%3};"
        : "+f"(d[0]), "+f"(d[1]), "+f"(d[2]), "+f"(d[3])
        : "r"(a[0]), "r"(a[1]), "r"(a[2]), "r"(a[3]), "r"(b[0]), "r"(b[1]));
}

// ---------------------------------------------------------------------------
// Pass 1: persistent single-pass fp16 tensor GEMM + exp + row sums + mask
// Block tile 128(M) x 64(N); warp grid 4(M) x 2(N); warp tile 32x32.
// Fragments via ldmatrix.x4; B double-buffered; reg prefetch of next tile.
// ---------------------------------------------------------------------------
__global__ void __launch_bounds__(THREADS, 2)
k_gemm(const float* __restrict__ x, const float* __restrict__ mda,
       const int* __restrict__ labels, float* __restrict__ out) {
    extern __shared__ char smem[];
    const uint32_t sb = (uint32_t)__cvta_generic_to_shared(smem);
    const int tid  = threadIdx.x;
    const int wid  = tid >> 5;
    const int lane = tid & 31;
    const int cta  = blockIdx.x;
    const int cnt  = (NTILES - cta + GRID - 1) / GRID;

    // prefetch indexing: thread owns (nl = (tid>>6) + 4j, k0 = 2*(tid&63))
    const int pk = (tid & 63) * 2;
    const int pn = tid >> 6;

    // ---- prefetch tile 0, packed to fp16x2 (16 regs) ----
    uint32_t pf[16];
    {
        const float* src = mda + (size_t)cta * NT * 129 + 1 + pk;
        const bool tail = (cta == NTILES - 1);
#pragma unroll
        for (int j = 0; j < 16; ++j) {
            int nl = pn + 4 * j;
            bool ok = !tail || (cta * NT + nl) < Ndim;
            float v0 = ok ? __ldcs(src + (size_t)nl * 129)     : 0.0f;
            float v1 = ok ? __ldcs(src + (size_t)nl * 129 + 1) : 0.0f;
            pf[j] = pack2(v0, v1);
        }
    }

    // ---- labels for mask rows this warp owns (16 regs) ----
    float lbl[16];
#pragma unroll
    for (int r = 0; r < 16; ++r) lbl[r] = (float)__ldg(labels + wid + r * 8);

    // ---- stage A = x (fp16, single copy) once ----
    {
        const float4* xv = reinterpret_cast<const float4*>(x);
#pragma unroll
        for (int i = tid; i < (Bdim * Ddim) / 4; i += THREADS) {
            float4 v = xv[i];
            int b = i >> 5, k = (i & 31) * 4;
            uint2 p = make_uint2(pack2(v.x, v.y), pack2(v.z, v.w));
            *(uint2*)(smem + SM_A + (size_t)b * PITCH + k * 2) = p;
        }
    }

    // ---- warp tiling / ldmatrix lane addressing ----
    const int wm = wid >> 1, wn = wid & 1;
    const int gid = lane >> 2, tg = lane & 3;
    // A: lanes 0-7 rows0-7/k0, 8-15 rows8-15/k0, 16-23 rows0-7/k8, 24-31 rows8-15/k8
    const uint32_t aAddr = sb + SM_A + (wm * 32 + (lane & 15)) * PITCH + (lane >> 4) * 16;
    // B: row = n, tiles: [n0-7,k0],[n0-7,k8],[n8-15,k0],[n8-15,k8]
    const uint32_t bLane = (uint32_t)((wn * 32 + (lane >> 4) * 8 + (lane & 7)) * PITCH
                                      + ((lane >> 3) & 1) * 16);

    float rs[2][2] = {{0.0f, 0.0f}, {0.0f, 0.0f}};   // running row sums

    for (int i = 0; i < cnt; ++i) {
        const int t  = cta + i * GRID;
        const int bi = i & 1;
        const int n0 = t * NT;
        char* bbuf = smem + SM_B + bi * 17408;

        // ---- store prefetched tile into B[bi] ----
        __syncthreads();   // B[bi] from iter i-2 no longer read
#pragma unroll
        for (int j = 0; j < 16; ++j) {
            int nl = pn + 4 * j;
            *(uint32_t*)(bbuf + (size_t)nl * PITCH + pk * 2) = pf[j];
        }

        // ---- prefetch next tile (hides DRAM under MMA) ----
        if (i + 1 < cnt) {
            const int tn = t + GRID;
            const float* src = mda + (size_t)tn * NT * 129 + 1 + pk;
            const bool tail = (tn == NTILES - 1);
#pragma unroll
            for (int j = 0; j < 16; ++j) {
                int nl = pn + 4 * j;
                bool ok = !tail || (tn * NT + nl) < Ndim;
                float v0 = ok ? __ldcs(src + (size_t)nl * 129)     : 0.0f;
                float v1 = ok ? __ldcs(src + (size_t)nl * 129 + 1) : 0.0f;
                pf[j] = pack2(v0, v1);
            }
        }
        __syncthreads();   // B[bi] ready

        // ---- MMA via ldmatrix fragments ----
        const uint32_t bAddr = sb + SM_B + bi * 17408 + bLane;
        float acc[2][4][4];
#pragma unroll
        for (int mi = 0; mi < 2; ++mi)
#pragma unroll
            for (int ni = 0; ni < 4; ++ni)
#pragma unroll
                for (int r = 0; r < 4; ++r) acc[mi][ni][r] = 0.0f;

#pragma unroll
        for (int ks = 0; ks < 8; ++ks) {
            uint32_t a0[4], a1[4], b0[4], b1[4];
            ldsm4(a0, aAddr + ks * 32);
            ldsm4(a1, aAddr + 16 * PITCH + ks * 32);
            ldsm4(b0, bAddr + ks * 32);
            ldsm4(b1, bAddr + 16 * PITCH + ks * 32);
            mma_f16(acc[0][0], a0, b0);     mma_f16(acc[0][1], a0, b0 + 2);
            mma_f16(acc[0][2], a0, b1);     mma_f16(acc[0][3], a0, b1 + 2);
            mma_f16(acc[1][0], a1, b0);     mma_f16(acc[1][1], a1, b0 + 2);
            mma_f16(acc[1][2], a1, b1);     mma_f16(acc[1][3], a1, b1 + 2);
        }

        // ---- epilogue: exp, store out, accumulate running row sums ----
#pragma unroll
        for (int mi = 0; mi < 2; ++mi) {
            const int m_lo = wm * 32 + mi * 16 + gid;
#pragma unroll
            for (int ni = 0; ni < 4; ++ni) {
                const int ng = n0 + wn * 32 + ni * 8 + tg * 2;
                const bool ok = ng < Ndim;
                float e0 = ok ? __expf(acc[mi][ni][0] * INV_T) : 0.0f;
                float e1 = ok ? __expf(acc[mi][ni][1] * INV_T) : 0.0f;
                float e2 = ok ? __expf(acc[mi][ni][2] * INV_T) : 0.0f;
                float e3 = ok ? __expf(acc[mi][ni][3] * INV_T) : 0.0f;
                if (ok) {
                    *(float2*)(out + (size_t)m_lo * Ndim + ng)       = make_float2(e0, e1);
                    *(float2*)(out + (size_t)(m_lo + 8) * Ndim + ng) = make_float2(e2, e3);
                }
                rs[mi][0] += e0 + e1;
                rs[mi][1] += e2 + e3;
            }
        }

        // ---- mask write for this tile (labels in registers) ----
        {
            const int n = n0 + lane * 2;
            if (n + 1 < Ndim) {
                float c0 = __ldg(mda + (size_t)n * 129);
                float c1 = __ldg(mda + (size_t)(n + 1) * 129);
                float* mbase = out + (size_t)Bdim * Ndim;
#pragma unroll
                for (int r = 0; r < 16; ++r) {
                    const int b = wid + r * 8;
                    float2 m = make_float2(c0 == lbl[r] ? 1.0f : 0.0f,
                                           c1 == lbl[r] ? 1.0f : 0.0f);
                    __stcs((float2*)(mbase + (size_t)b * Ndim + n), m);
                }
            }
        }
    }

    // ---- fold running sums ----
    float* racc = (float*)(smem + SM_RACC);
    __syncthreads();
#pragma unroll
    for (int mi = 0; mi < 2; ++mi) {
#pragma unroll
        for (int o = 1; o <= 2; o <<= 1) {
            rs[mi][0] += __shfl_xor_sync(0xffffffffu, rs[mi][0], o);
            rs[mi][1] += __shfl_xor_sync(0xffffffffu, rs[mi][1], o);
        }
        if (tg == 0) {
            const int m_lo = wm * 32 + mi * 16 + gid;
            racc[wn * 128 + m_lo]     = rs[mi][0];
            racc[wn * 128 + m_lo + 8] = rs[mi][1];
        }
    }
    __syncthreads();
    if (tid < 128)
        g_partial[(size_t)tid * GRID + cta] = racc[tid] + racc[128 + tid];
}

// ---------------------------------------------------------------------------
// Pass 2: deterministic reduction of per-CTA partials
// ---------------------------------------------------------------------------
__global__ void k_reduce() {
    __shared__ float sh[256];
    const int b = blockIdx.x, t = threadIdx.x;
    float s = 0.0f;
    for (int i = t; i < GRID; i += 256) s += g_partial[(size_t)b * GRID + i];
    sh[t] = s;
    __syncthreads();
    for (int o = 128; o > 0; o >>= 1) {
        if (t < o) sh[t] += sh[t + o];
        __syncthreads();
    }
    if (t == 0) g_invsum[b] = 1.0f / sh[0];
}

// ---------------------------------------------------------------------------
// Pass 3: in-place normalize (mask already written by k_gemm)
// ---------------------------------------------------------------------------
__global__ void __launch_bounds__(256)
k_norm(float* __restrict__ out) {
    const int b = blockIdx.y;
    const float inv = g_invsum[b];
    const int f0 = blockIdx.x * 1024 + threadIdx.x;
    const int NF4 = Ndim / 4;

    float4* orow = reinterpret_cast<float4*>(out + (size_t)b * Ndim);

    float4 v[4];
    bool ok[4];
#pragma unroll
    for (int j = 0; j < 4; ++j) {
        int f = f0 + 256 * j;
        ok[j] = f < NF4;
        if (ok[j]) v[j] = orow[f];
    }
#pragma unroll
    for (int j = 0; j < 4; ++j) {
        if (!ok[j]) continue;
        int f = f0 + 256 * j;
        float4 t = v[j];
        t.x *= inv; t.y *= inv; t.z *= inv; t.w *= inv;
        orow[f] = t;
    }
}

// ---------------------------------------------------------------------------
extern "C" void kernel_launch(void* const* d_in, const int* in_sizes, int n_in,
                              void* d_out, int out_size) {
    const float* x      = (const float*)d_in[0];   // [128,128]
    const int*   labels = (const int*)  d_in[2];   // [128]
    const float* mda    = (const float*)d_in[3];   // [100000,129]
    float*       out    = (float*)d_out;

    cudaFuncSetAttribute(k_gemm, cudaFuncAttributeMaxDynamicSharedMemorySize, SM_TOTAL);

    k_gemm<<<GRID, THREADS, SM_TOTAL>>>(x, mda, labels, out);
    k_reduce<<<Bdim, 256>>>();
    dim3 ngrid((Ndim / 4 + 1023) / 1024, Bdim);
    k_norm<<<ngrid, 256>>>(out);
}